// round 15
// baseline (speedup 1.0000x reference)
#include <cuda_runtime.h>
#include <cuda_fp16.h>
#include <stdint.h>

// ---------------- static scratch (no allocation allowed) ----------------
#define MAXN 50176
__device__ __align__(16) uint16_t g_xh[MAXN * 128];     // x in fp16
__device__ __align__(16) uint16_t g_neighh[MAXN * 128]; // neighbor mean in fp16
__device__ float    g_WgT[128 * 128];                   // Wg^T for deg==0 fixup
__device__ __align__(16) uint16_t g_Bh[128 * 256];      // fp16 B = [Wg+Ws | Wl]
__device__ int      g_off[MAXN];

__device__ __forceinline__ uint32_t smem_u32(const void* p) {
    uint32_t a;
    asm("{ .reg .u64 t; cvta.to.shared.u64 t, %1; cvt.u32.u64 %0, t; }" : "=r"(a) : "l"(p));
    return a;
}

__device__ __forceinline__ float elu_f(float v) {
    return (v > 0.f) ? v : (__expf(v) - 1.f);
}

#define LDSM_X4(r0, r1, r2, r3, addr) \
    asm volatile("ldmatrix.sync.aligned.m8n8.x4.shared.b16 {%0,%1,%2,%3}, [%4];" \
        : "=r"(r0), "=r"(r1), "=r"(r2), "=r"(r3) : "r"(addr))

#define MMA_F16(d, a, b0, b1) \
    asm volatile("mma.sync.aligned.m16n8k16.row.col.f32.f16.f16.f32 " \
        "{%0,%1,%2,%3}, {%4,%5,%6,%7}, {%8,%9}, {%0,%1,%2,%3};" \
        : "+f"((d)[0]), "+f"((d)[1]), "+f"((d)[2]), "+f"((d)[3]) \
        : "r"((a)[0]), "r"((a)[1]), "r"((a)[2]), "r"((a)[3]), "r"(b0), "r"(b1))

#define CP_ASYNC16(dst, src, sz) \
    asm volatile("cp.async.ca.shared.global [%0], [%1], 16, %2;" \
        :: "r"(dst), "l"(src), "r"(sz) : "memory")
#define CP_COMMIT()  asm volatile("cp.async.commit_group;" ::: "memory")
#define CP_WAIT0()   asm volatile("cp.async.wait_group 0;" ::: "memory")
#define CP_WAIT1()   asm volatile("cp.async.wait_group 1;" ::: "memory")

// ---------------- kernel 1: B fp16 + WgT + x->fp16 + edge offsets ----------------
__global__ void prep_all(const float* __restrict__ x, const float* __restrict__ Wg,
                         const float* __restrict__ Wl, const float* __restrict__ Ws,
                         const int* __restrict__ dst, const int* __restrict__ deg,
                         int N, int E) {
    int i = blockIdx.x * blockDim.x + threadIdx.x;
    if (i < 128 * 256) {
        int o = i >> 8, k = i & 255;
        float v = (k < 128) ? (Wg[o * 128 + k] + Ws[o * 128 + k]) : Wl[o * 128 + (k - 128)];
        g_Bh[i] = __half_as_ushort(__float2half_rn(v));
    }
    if (i < 128 * 128) {
        int o = i >> 7, k = i & 127;
        g_WgT[k * 128 + o] = Wg[i];
    }
    if (i < N * 32) {
        float4 v = ((const float4*)x)[i];
        half2 a = __floats2half2_rn(v.x, v.y);
        half2 b = __floats2half2_rn(v.z, v.w);
        ((uint2*)g_xh)[i] = make_uint2(*(const uint32_t*)&a, *(const uint32_t*)&b);
    }
    if (i < N) {
        int d = deg[i];
        int lo = 0;
        if (d > 0) {
            int hi = E;
            while (lo < hi) { int mid = (lo + hi) >> 1; if (dst[mid] < i) lo = mid + 1; else hi = mid; }
        }
        g_off[i] = lo;
    }
}

// ---------------- kernel 2: neighbor mean — paired-edge 16B gathers ----------------
__global__ void aggregate(const int* __restrict__ src, const int* __restrict__ deg, int N) {
    int node = (int)((blockIdx.x * blockDim.x + threadIdx.x) >> 5);
    int lane = threadIdx.x & 31;
    if (node >= N) return;
    int d = deg[node];                 // uniform across warp (0..32)
    int start = g_off[node];
    int halfsel = lane >> 4;           // which edge of the pair
    int pos = lane & 15;               // 16B unit within the 256B row

    float acc[8];
    #pragma unroll
    for (int q = 0; q < 8; q++) acc[q] = 0.f;

    int myidx = (lane < d) ? __ldg(src + start + lane) : 0;
    const uint4* x4 = (const uint4*)g_xh;

    int j = 0;
    #pragma unroll 4
    for (; j + 1 < d; j += 2) {
        int s = __shfl_sync(0xffffffffu, myidx, j + halfsel);
        uint4 w = x4[(size_t)s * 16 + pos];
        float2 p;
        p = __half22float2(*(const half2*)&w.x); acc[0] += p.x; acc[1] += p.y;
        p = __half22float2(*(const half2*)&w.y); acc[2] += p.x; acc[3] += p.y;
        p = __half22float2(*(const half2*)&w.z); acc[4] += p.x; acc[5] += p.y;
        p = __half22float2(*(const half2*)&w.w); acc[6] += p.x; acc[7] += p.y;
    }
    if (j < d) {                       // odd leftover edge
        int s = __shfl_sync(0xffffffffu, myidx, d - 1);
        if (halfsel == 0) {
            uint4 w = x4[(size_t)s * 16 + pos];
            float2 p;
            p = __half22float2(*(const half2*)&w.x); acc[0] += p.x; acc[1] += p.y;
            p = __half22float2(*(const half2*)&w.y); acc[2] += p.x; acc[3] += p.y;
            p = __half22float2(*(const half2*)&w.z); acc[4] += p.x; acc[5] += p.y;
            p = __half22float2(*(const half2*)&w.w); acc[6] += p.x; acc[7] += p.y;
        }
    }

    #pragma unroll
    for (int q = 0; q < 8; q++)
        acc[q] += __shfl_xor_sync(0xffffffffu, acc[q], 16);

    if (lane < 16) {
        float inv = (d > 0) ? (1.0f / (float)d) : 0.0f;
        half2 h0 = __floats2half2_rn(acc[0] * inv, acc[1] * inv);
        half2 h1 = __floats2half2_rn(acc[2] * inv, acc[3] * inv);
        half2 h2 = __floats2half2_rn(acc[4] * inv, acc[5] * inv);
        half2 h3 = __floats2half2_rn(acc[6] * inv, acc[7] * inv);
        uint4 o = make_uint4(*(const uint32_t*)&h0, *(const uint32_t*)&h1,
                             *(const uint32_t*)&h2, *(const uint32_t*)&h3);
        ((uint4*)g_neighh)[(size_t)node * 16 + pos] = o;
    }
}

// ---------------- kernel 3: fp16 HMMA GEMM, cross-tile double-buffered A ----------------
// out = elu([x|neigh]h @ Bh^T + b).  16 warps (4m x 4n), tile 128x128.
// Bias folded into accumulator init.
#define SM_BH    0
#define SM_A     65536           /* 2 bufs x 64KB */
#define SM_TOTAL 196608

__device__ __forceinline__ void stage_tile(uint32_t sb, const char* xb, const char* nb,
                                           int base, int arow, int aq, uint32_t buf, int N) {
    int node = base + arow;
    bool valid = node < N;
    uint32_t srcsz = valid ? 16u : 0u;
    size_t rowoff = (size_t)(valid ? node : 0) * 256;
    uint32_t sw0 = (uint32_t)(((aq * 2 + 0) ^ (arow & 7)) * 16);
    uint32_t sw1 = (uint32_t)(((aq * 2 + 1) ^ (arow & 7)) * 16);
    #pragma unroll
    for (int kb = 0; kb < 4; kb++) {
        const char* s = (kb < 2 ? xb : nb) + rowoff + (kb & 1) * 128 + aq * 32;
        uint32_t dbase = sb + SM_A + buf * 65536 + (uint32_t)kb * 16384 + (uint32_t)arow * 128;
        CP_ASYNC16(dbase + sw0, s, srcsz);
        CP_ASYNC16(dbase + sw1, s + 16, srcsz);
    }
    CP_COMMIT();
}

__global__ void __launch_bounds__(512, 1)
gemm_mma(const float* __restrict__ bias, float* __restrict__ out, int N) {
    extern __shared__ char sm_[];
    uint32_t sb = smem_u32(sm_);
    int tid  = threadIdx.x;
    int wid  = tid >> 5;
    int lane = tid & 31;
    int m_warp = (wid & 3) * 32;
    int n_warp = (wid >> 2) * 32;

    // ---- load B into swizzled smem (once per CTA) ----
    {
        const uint4* bh = (const uint4*)g_Bh;   // 128 rows x 32 16B-units
        #pragma unroll
        for (int it = 0; it < 8; it++) {
            int ci = it * 512 + tid;             // 0..4095
            int n = ci >> 5, c = ci & 31;
            int sw = (c & ~7) | ((c ^ n) & 7);
            ((uint4*)(sm_ + SM_BH))[n * 32 + sw] = bh[ci];
        }
    }

    int a_row0  = m_warp + (lane & 15);
    int a_khalf = (lane >> 4) & 1;
    int b_nl    = (lane & 7) + ((lane >> 4) & 1) * 8;
    int b_khalf = (lane >> 3) & 1;

    int arow = tid >> 2;          // staging row 0..127
    int aq   = tid & 3;           // 32B quarter of the 128B chunk-row
    const char* xb = (const char*)g_xh;
    const char* nb = (const char*)g_neighh;

    // per-thread bias registers (columns fixed for this thread across all tiles)
    int t = lane & 3;
    float bv0[4], bv1[4];
    #pragma unroll
    for (int nt = 0; nt < 4; nt++) {
        int col = n_warp + nt * 8 + t * 2;
        bv0[nt] = __ldg(bias + col);
        bv1[nt] = __ldg(bias + col + 1);
    }

    int ntiles = (N + 127) >> 7;
    uint32_t buf = 0;
    int c = blockIdx.x;
    if (c < ntiles) stage_tile(sb, xb, nb, c * 128, arow, aq, 0, N);

    for (; c < ntiles; c += gridDim.x) {
        int base = c * 128;
        int cn = c + gridDim.x;
        bool has_next = (cn < ntiles);
        if (has_next) {
            stage_tile(sb, xb, nb, cn * 128, arow, aq, buf ^ 1, N);
            CP_WAIT1();          // current buf's group done; prefetch in flight
        } else {
            CP_WAIT0();
        }
        __syncthreads();

        float d[2][4][4];
        #pragma unroll
        for (int mt = 0; mt < 2; mt++)
            #pragma unroll
            for (int nt = 0; nt < 4; nt++) {
                d[mt][nt][0] = bv0[nt]; d[mt][nt][1] = bv1[nt];
                d[mt][nt][2] = bv0[nt]; d[mt][nt][3] = bv1[nt];
            }

        uint32_t abuf = sb + SM_A + buf * 65536;
        #pragma unroll
        for (int kb = 0; kb < 4; kb++) {
            uint32_t abase = abuf + (uint32_t)kb * 16384;
            #pragma unroll
            for (int step = 0; step < 4; step++) {
                uint32_t a_[2][4];
                #pragma unroll
                for (int mt = 0; mt < 2; mt++) {
                    int r = a_row0 + mt * 16;
                    int cb = (step * 2 + a_khalf) ^ (r & 7);
                    LDSM_X4(a_[mt][0], a_[mt][1], a_[mt][2], a_[mt][3],
                            abase + (uint32_t)(r * 128 + cb * 16));
                }
                uint32_t bh_[2][4];
                #pragma unroll
                for (int ng = 0; ng < 2; ng++) {
                    int n = n_warp + ng * 16 + b_nl;
                    int cc = kb * 8 + step * 2 + b_khalf;
                    int sw = (cc & ~7) | ((cc ^ n) & 7);
                    LDSM_X4(bh_[ng][0], bh_[ng][1], bh_[ng][2], bh_[ng][3],
                            sb + SM_BH + (uint32_t)(n * 512 + sw * 16));
                }
                #pragma unroll
                for (int mt = 0; mt < 2; mt++)
                    #pragma unroll
                    for (int ng = 0; ng < 2; ng++)
                        #pragma unroll
                        for (int sub = 0; sub < 2; sub++)
                            MMA_F16(d[mt][ng * 2 + sub], a_[mt],
                                    bh_[ng][sub * 2], bh_[ng][sub * 2 + 1]);
            }
        }

        // ---- epilogue: ELU + store (bias already in accumulators) ----
        int g = lane >> 2;
        #pragma unroll
        for (int mt = 0; mt < 2; mt++) {
            int row0 = base + m_warp + mt * 16 + g;
            #pragma unroll
            for (int nt = 0; nt < 4; nt++) {
                int col = n_warp + nt * 8 + t * 2;
                #pragma unroll
                for (int hrow = 0; hrow < 2; hrow++) {
                    int row = row0 + hrow * 8;
                    if (row < N) {
                        float v0 = elu_f(d[mt][nt][hrow * 2 + 0]);
                        float v1 = elu_f(d[mt][nt][hrow * 2 + 1]);
                        *(float2*)(out + (size_t)row * 128 + col) = make_float2(v0, v1);
                    }
                }
            }
        }
        __syncthreads();   // readers done before next iter overwrites this buf
        buf ^= 1;
    }
}

// ---------------- kernel 4: deg==0 fixup — block-cooperative ballot compaction ------
// 256 threads scan 256 nodes (coalesced deg loads); each warp GEMVs its flagged nodes.
__global__ void fixup_deg0(const float* __restrict__ x, const float* __restrict__ bias,
                           const int* __restrict__ deg, float* __restrict__ out, int N) {
    int lane = threadIdx.x & 31;
    int wbase = blockIdx.x * 256 + (int)(threadIdx.x & ~31);   // this warp's 32 nodes
    if (wbase >= N) return;

    int n32 = wbase + lane;
    int dg = (n32 < N) ? __ldg(deg + n32) : 1;
    unsigned mask = __ballot_sync(0xffffffffu, dg == 0);
    if (!mask) return;

    const float4* wt = (const float4*)g_WgT;
    float4 bb = ((const float4*)bias)[lane];

    while (mask) {
        int b = __ffs(mask) - 1;
        mask &= mask - 1;
        int node = wbase + b;
        const float* xr = x + (size_t)node * 128;
        float4 acc = make_float4(0.f, 0.f, 0.f, 0.f);
        #pragma unroll 16
        for (int k = 0; k < 128; k++) {
            float a = __ldg(xr + k);
            float4 w = wt[k * 32 + lane];
            acc.x = fmaf(a, w.x, acc.x);
            acc.y = fmaf(a, w.y, acc.y);
            acc.z = fmaf(a, w.z, acc.z);
            acc.w = fmaf(a, w.w, acc.w);
        }
        acc.x = elu_f(acc.x + bb.x);
        acc.y = elu_f(acc.y + bb.y);
        acc.z = elu_f(acc.z + bb.z);
        acc.w = elu_f(acc.w + bb.w);
        ((float4*)(out + (size_t)node * 128))[lane] = acc;
    }
}

extern "C" void kernel_launch(void* const* d_in, const int* in_sizes, int n_in,
                              void* d_out, int out_size) {
    const float* x  = (const float*)d_in[0];
    const float* Wg = (const float*)d_in[1];
    const float* Wl = (const float*)d_in[2];
    const float* Ws = (const float*)d_in[3];
    const float* b  = (const float*)d_in[4];
    const int* src  = (const int*)d_in[5];
    const int* dst  = (const int*)d_in[6];
    const int* deg  = (const int*)d_in[7];
    int E = in_sizes[5];
    int N = in_sizes[7];
    float* out = (float*)d_out;

    int sm_count = 148;
    cudaDeviceGetAttribute(&sm_count, cudaDevAttrMultiProcessorCount, 0);

    cudaFuncSetAttribute(gemm_mma, cudaFuncAttributeMaxDynamicSharedMemorySize, SM_TOTAL);

    prep_all<<<(N * 32 + 255) / 256, 256>>>(x, Wg, Wl, Ws, dst, deg, N, E);
    aggregate<<<(N + 7) / 8, 256>>>(src, deg, N);
    gemm_mma<<<sm_count, 512, SM_TOTAL>>>(b, out, N);
    fixup_deg0<<<(N + 255) / 256, 256>>>(x, b, deg, out, N);
}

// round 16
// speedup vs baseline: 1.2476x; 1.2476x over previous
#include <cuda_runtime.h>
#include <cuda_fp16.h>
#include <stdint.h>

// ---------------- static scratch (no allocation allowed) ----------------
#define MAXN 50176
__device__ __align__(16) uint16_t g_xh[MAXN * 128];     // x in fp16
__device__ __align__(16) uint16_t g_neighh[MAXN * 128]; // neighbor mean in fp16
__device__ float    g_WgT[128 * 128];                   // Wg^T for deg==0 fixup
__device__ __align__(16) uint16_t g_Bh[128 * 256];      // fp16 B = [Wg+Ws | Wl]
__device__ int      g_off[MAXN];

__device__ __forceinline__ uint32_t smem_u32(const void* p) {
    uint32_t a;
    asm("{ .reg .u64 t; cvta.to.shared.u64 t, %1; cvt.u32.u64 %0, t; }" : "=r"(a) : "l"(p));
    return a;
}

__device__ __forceinline__ float elu_f(float v) {
    return (v > 0.f) ? v : (__expf(v) - 1.f);
}

#define LDSM_X4(r0, r1, r2, r3, addr) \
    asm volatile("ldmatrix.sync.aligned.m8n8.x4.shared.b16 {%0,%1,%2,%3}, [%4];" \
        : "=r"(r0), "=r"(r1), "=r"(r2), "=r"(r3) : "r"(addr))

#define MMA_F16(d, a, b0, b1) \
    asm volatile("mma.sync.aligned.m16n8k16.row.col.f32.f16.f16.f32 " \
        "{%0,%1,%2,%3}, {%4,%5,%6,%7}, {%8,%9}, {%0,%1,%2,%3};" \
        : "+f"((d)[0]), "+f"((d)[1]), "+f"((d)[2]), "+f"((d)[3]) \
        : "r"((a)[0]), "r"((a)[1]), "r"((a)[2]), "r"((a)[3]), "r"(b0), "r"(b1))

#define CP_ASYNC16(dst, src, sz) \
    asm volatile("cp.async.ca.shared.global [%0], [%1], 16, %2;" \
        :: "r"(dst), "l"(src), "r"(sz) : "memory")
#define CP_COMMIT()  asm volatile("cp.async.commit_group;" ::: "memory")
#define CP_WAIT0()   asm volatile("cp.async.wait_group 0;" ::: "memory")
#define CP_WAIT1()   asm volatile("cp.async.wait_group 1;" ::: "memory")

// ---------------- kernel 1: B fp16 + WgT + x->fp16 + edge offsets ----------------
__global__ void prep_all(const float* __restrict__ x, const float* __restrict__ Wg,
                         const float* __restrict__ Wl, const float* __restrict__ Ws,
                         const int* __restrict__ dst, const int* __restrict__ deg,
                         int N, int E) {
    int i = blockIdx.x * blockDim.x + threadIdx.x;
    if (i < 128 * 256) {
        int o = i >> 8, k = i & 255;
        float v = (k < 128) ? (Wg[o * 128 + k] + Ws[o * 128 + k]) : Wl[o * 128 + (k - 128)];
        g_Bh[i] = __half_as_ushort(__float2half_rn(v));
    }
    if (i < 128 * 128) {
        int o = i >> 7, k = i & 127;
        g_WgT[k * 128 + o] = Wg[i];
    }
    if (i < N * 32) {
        float4 v = ((const float4*)x)[i];
        half2 a = __floats2half2_rn(v.x, v.y);
        half2 b = __floats2half2_rn(v.z, v.w);
        ((uint2*)g_xh)[i] = make_uint2(*(const uint32_t*)&a, *(const uint32_t*)&b);
    }
    if (i < N) {
        int d = deg[i];
        int lo = 0;
        if (d > 0) {
            int hi = E;
            while (lo < hi) { int mid = (lo + hi) >> 1; if (dst[mid] < i) lo = mid + 1; else hi = mid; }
        }
        g_off[i] = lo;
    }
}

// ---------------- kernel 2: neighbor mean — paired-edge 16B gathers ----------------
__global__ void aggregate(const int* __restrict__ src, const int* __restrict__ deg, int N) {
    int node = (int)((blockIdx.x * blockDim.x + threadIdx.x) >> 5);
    int lane = threadIdx.x & 31;
    if (node >= N) return;
    int d = deg[node];                 // uniform across warp (0..32)
    int start = g_off[node];
    int halfsel = lane >> 4;           // which edge of the pair
    int pos = lane & 15;               // 16B unit within the 256B row

    float acc[8];
    #pragma unroll
    for (int q = 0; q < 8; q++) acc[q] = 0.f;

    int myidx = (lane < d) ? __ldg(src + start + lane) : 0;
    const uint4* x4 = (const uint4*)g_xh;

    int j = 0;
    #pragma unroll 4
    for (; j + 1 < d; j += 2) {
        int s = __shfl_sync(0xffffffffu, myidx, j + halfsel);
        uint4 w = x4[(size_t)s * 16 + pos];
        float2 p;
        p = __half22float2(*(const half2*)&w.x); acc[0] += p.x; acc[1] += p.y;
        p = __half22float2(*(const half2*)&w.y); acc[2] += p.x; acc[3] += p.y;
        p = __half22float2(*(const half2*)&w.z); acc[4] += p.x; acc[5] += p.y;
        p = __half22float2(*(const half2*)&w.w); acc[6] += p.x; acc[7] += p.y;
    }
    if (j < d) {                       // odd leftover edge
        int s = __shfl_sync(0xffffffffu, myidx, d - 1);
        if (halfsel == 0) {
            uint4 w = x4[(size_t)s * 16 + pos];
            float2 p;
            p = __half22float2(*(const half2*)&w.x); acc[0] += p.x; acc[1] += p.y;
            p = __half22float2(*(const half2*)&w.y); acc[2] += p.x; acc[3] += p.y;
            p = __half22float2(*(const half2*)&w.z); acc[4] += p.x; acc[5] += p.y;
            p = __half22float2(*(const half2*)&w.w); acc[6] += p.x; acc[7] += p.y;
        }
    }

    #pragma unroll
    for (int q = 0; q < 8; q++)
        acc[q] += __shfl_xor_sync(0xffffffffu, acc[q], 16);

    if (lane < 16) {
        float inv = (d > 0) ? (1.0f / (float)d) : 0.0f;
        half2 h0 = __floats2half2_rn(acc[0] * inv, acc[1] * inv);
        half2 h1 = __floats2half2_rn(acc[2] * inv, acc[3] * inv);
        half2 h2 = __floats2half2_rn(acc[4] * inv, acc[5] * inv);
        half2 h3 = __floats2half2_rn(acc[6] * inv, acc[7] * inv);
        uint4 o = make_uint4(*(const uint32_t*)&h0, *(const uint32_t*)&h1,
                             *(const uint32_t*)&h2, *(const uint32_t*)&h3);
        ((uint4*)g_neighh)[(size_t)node * 16 + pos] = o;
    }
}

// ---------------- kernel 3: fp16 HMMA GEMM, cross-tile double-buffered A ----------------
// out = elu([x|neigh]h @ Bh^T + b).  16 warps (4m x 4n), tile 128x128.
// Bias folded into accumulator init.
#define SM_BH    0
#define SM_A     65536           /* 2 bufs x 64KB */
#define SM_TOTAL 196608

__device__ __forceinline__ void stage_tile(uint32_t sb, const char* xb, const char* nb,
                                           int base, int arow, int aq, uint32_t buf, int N) {
    int node = base + arow;
    bool valid = node < N;
    uint32_t srcsz = valid ? 16u : 0u;
    size_t rowoff = (size_t)(valid ? node : 0) * 256;
    uint32_t sw0 = (uint32_t)(((aq * 2 + 0) ^ (arow & 7)) * 16);
    uint32_t sw1 = (uint32_t)(((aq * 2 + 1) ^ (arow & 7)) * 16);
    #pragma unroll
    for (int kb = 0; kb < 4; kb++) {
        const char* s = (kb < 2 ? xb : nb) + rowoff + (kb & 1) * 128 + aq * 32;
        uint32_t dbase = sb + SM_A + buf * 65536 + (uint32_t)kb * 16384 + (uint32_t)arow * 128;
        CP_ASYNC16(dbase + sw0, s, srcsz);
        CP_ASYNC16(dbase + sw1, s + 16, srcsz);
    }
    CP_COMMIT();
}

__global__ void __launch_bounds__(512, 1)
gemm_mma(const float* __restrict__ bias, float* __restrict__ out, int N) {
    extern __shared__ char sm_[];
    uint32_t sb = smem_u32(sm_);
    int tid  = threadIdx.x;
    int wid  = tid >> 5;
    int lane = tid & 31;
    int m_warp = (wid & 3) * 32;
    int n_warp = (wid >> 2) * 32;

    // ---- load B into swizzled smem (once per CTA) ----
    {
        const uint4* bh = (const uint4*)g_Bh;   // 128 rows x 32 16B-units
        #pragma unroll
        for (int it = 0; it < 8; it++) {
            int ci = it * 512 + tid;             // 0..4095
            int n = ci >> 5, c = ci & 31;
            int sw = (c & ~7) | ((c ^ n) & 7);
            ((uint4*)(sm_ + SM_BH))[n * 32 + sw] = bh[ci];
        }
    }

    int a_row0  = m_warp + (lane & 15);
    int a_khalf = (lane >> 4) & 1;
    int b_nl    = (lane & 7) + ((lane >> 4) & 1) * 8;
    int b_khalf = (lane >> 3) & 1;

    int arow = tid >> 2;          // staging row 0..127
    int aq   = tid & 3;           // 32B quarter of the 128B chunk-row
    const char* xb = (const char*)g_xh;
    const char* nb = (const char*)g_neighh;

    // per-thread bias registers (columns fixed for this thread across all tiles)
    int t = lane & 3;
    float bv0[4], bv1[4];
    #pragma unroll
    for (int nt = 0; nt < 4; nt++) {
        int col = n_warp + nt * 8 + t * 2;
        bv0[nt] = __ldg(bias + col);
        bv1[nt] = __ldg(bias + col + 1);
    }

    int ntiles = (N + 127) >> 7;
    uint32_t buf = 0;
    int c = blockIdx.x;
    if (c < ntiles) stage_tile(sb, xb, nb, c * 128, arow, aq, 0, N);

    for (; c < ntiles; c += gridDim.x) {
        int base = c * 128;
        int cn = c + gridDim.x;
        bool has_next = (cn < ntiles);
        if (has_next) {
            stage_tile(sb, xb, nb, cn * 128, arow, aq, buf ^ 1, N);
            CP_WAIT1();          // current buf's group done; prefetch in flight
        } else {
            CP_WAIT0();
        }
        __syncthreads();

        float d[2][4][4];
        #pragma unroll
        for (int mt = 0; mt < 2; mt++)
            #pragma unroll
            for (int nt = 0; nt < 4; nt++) {
                d[mt][nt][0] = bv0[nt]; d[mt][nt][1] = bv1[nt];
                d[mt][nt][2] = bv0[nt]; d[mt][nt][3] = bv1[nt];
            }

        uint32_t abuf = sb + SM_A + buf * 65536;
        #pragma unroll
        for (int kb = 0; kb < 4; kb++) {
            uint32_t abase = abuf + (uint32_t)kb * 16384;
            #pragma unroll
            for (int step = 0; step < 4; step++) {
                uint32_t a_[2][4];
                #pragma unroll
                for (int mt = 0; mt < 2; mt++) {
                    int r = a_row0 + mt * 16;
                    int cb = (step * 2 + a_khalf) ^ (r & 7);
                    LDSM_X4(a_[mt][0], a_[mt][1], a_[mt][2], a_[mt][3],
                            abase + (uint32_t)(r * 128 + cb * 16));
                }
                uint32_t bh_[2][4];
                #pragma unroll
                for (int ng = 0; ng < 2; ng++) {
                    int n = n_warp + ng * 16 + b_nl;
                    int cc = kb * 8 + step * 2 + b_khalf;
                    int sw = (cc & ~7) | ((cc ^ n) & 7);
                    LDSM_X4(bh_[ng][0], bh_[ng][1], bh_[ng][2], bh_[ng][3],
                            sb + SM_BH + (uint32_t)(n * 512 + sw * 16));
                }
                #pragma unroll
                for (int mt = 0; mt < 2; mt++)
                    #pragma unroll
                    for (int ng = 0; ng < 2; ng++)
                        #pragma unroll
                        for (int sub = 0; sub < 2; sub++)
                            MMA_F16(d[mt][ng * 2 + sub], a_[mt],
                                    bh_[ng][sub * 2], bh_[ng][sub * 2 + 1]);
            }
        }

        // ---- epilogue: ELU + store (bias already in accumulators) ----
        int g = lane >> 2;
        #pragma unroll
        for (int mt = 0; mt < 2; mt++) {
            int row0 = base + m_warp + mt * 16 + g;
            #pragma unroll
            for (int nt = 0; nt < 4; nt++) {
                int col = n_warp + nt * 8 + t * 2;
                #pragma unroll
                for (int hrow = 0; hrow < 2; hrow++) {
                    int row = row0 + hrow * 8;
                    if (row < N) {
                        float v0 = elu_f(d[mt][nt][hrow * 2 + 0]);
                        float v1 = elu_f(d[mt][nt][hrow * 2 + 1]);
                        *(float2*)(out + (size_t)row * 128 + col) = make_float2(v0, v1);
                    }
                }
            }
        }
        __syncthreads();   // readers done before next iter overwrites this buf
        buf ^= 1;
    }
}

// ---------------- kernel 4: deg==0 fixup, one node per warp, early exit ----------------
__global__ void fixup_deg0(const float* __restrict__ x, const float* __restrict__ bias,
                           const int* __restrict__ deg, float* __restrict__ out, int N) {
    int node = (int)((blockIdx.x * blockDim.x + threadIdx.x) >> 5);
    int lane = threadIdx.x & 31;
    if (node >= N) return;
    if (__ldg(deg + node) != 0) return;

    const float* xr = x + (size_t)node * 128;
    const float4* wt = (const float4*)g_WgT;
    float4 acc = make_float4(0.f, 0.f, 0.f, 0.f);
    #pragma unroll 16
    for (int k = 0; k < 128; k++) {
        float a = __ldg(xr + k);
        float4 w = wt[k * 32 + lane];
        acc.x = fmaf(a, w.x, acc.x);
        acc.y = fmaf(a, w.y, acc.y);
        acc.z = fmaf(a, w.z, acc.z);
        acc.w = fmaf(a, w.w, acc.w);
    }
    float4 bb = ((const float4*)bias)[lane];
    acc.x = elu_f(acc.x + bb.x);
    acc.y = elu_f(acc.y + bb.y);
    acc.z = elu_f(acc.z + bb.z);
    acc.w = elu_f(acc.w + bb.w);
    ((float4*)(out + (size_t)node * 128))[lane] = acc;
}

extern "C" void kernel_launch(void* const* d_in, const int* in_sizes, int n_in,
                              void* d_out, int out_size) {
    const float* x  = (const float*)d_in[0];
    const float* Wg = (const float*)d_in[1];
    const float* Wl = (const float*)d_in[2];
    const float* Ws = (const float*)d_in[3];
    const float* b  = (const float*)d_in[4];
    const int* src  = (const int*)d_in[5];
    const int* dst  = (const int*)d_in[6];
    const int* deg  = (const int*)d_in[7];
    int E = in_sizes[5];
    int N = in_sizes[7];
    float* out = (float*)d_out;

    int sm_count = 148;
    cudaDeviceGetAttribute(&sm_count, cudaDevAttrMultiProcessorCount, 0);

    cudaFuncSetAttribute(gemm_mma, cudaFuncAttributeMaxDynamicSharedMemorySize, SM_TOTAL);

    prep_all<<<(N * 32 + 255) / 256, 256>>>(x, Wg, Wl, Ws, dst, deg, N, E);
    aggregate<<<(N + 7) / 8, 256>>>(src, deg, N);
    gemm_mma<<<sm_count, 512, SM_TOTAL>>>(b, out, N);
    fixup_deg0<<<(N * 32 + 255) / 256, 256>>>(x, b, deg, out, N);
}